// round 16
// baseline (speedup 1.0000x reference)
#include <cuda_runtime.h>
#include <cuda_fp16.h>
#include <cstdint>

#define NB   16
#define CIN  256
#define COUT 256
#define KS   5
#define SPK  128
#define TLEN 8192

#define OTI  64      // o tile per block (2 o-warps)
#define TTI  256     // t tile per block (4 t-warps)
#define ICH  16      // i chunk
#define XR   24      // padded row pitch (48B -> 16B-aligned halves)
#define XT   260     // xs rows (t range: tile + 4 pad)
#define NCH  16      // CIN / ICH
#define NTH  256

#define XS_ST (XT * XR)              // 6240 elems per stage
#define WS_ST (KS * OTI * XR)        // 7680 elems per stage
#define SMEM_BYTES ((2 * XS_ST + 2 * WS_ST) * 2)   // 55680

// scratch (no cudaMalloc allowed)
__device__ float g_s[NB * CIN];
__device__ __half g_wm[(size_t)NB * KS * COUT * CIN];        // [b][k][o][i]

// ---------------------------------------------------------------------------
// style GEMV, one warp per (b, i); block 0 copies the c_trg passthrough tail.
__global__ __launch_bounds__(256)
void style_kernel(const float* __restrict__ c_trg,
                  const float* __restrict__ style_w,
                  const float* __restrict__ style_b,
                  float* __restrict__ out_tail, int n_tail) {
    int v = blockIdx.x * 8 + (threadIdx.x >> 5);   // warp index: b*CIN + i
    int lane = threadIdx.x & 31;
    int b = v >> 8;
    int i = v & 255;
    const float* c = c_trg + b * SPK;
    const float* w = style_w + i * SPK;
    float acc = 0.f;
#pragma unroll
    for (int j = 0; j < 4; ++j) {
        int idx = lane + j * 32;
        acc += c[idx] * w[idx];
    }
#pragma unroll
    for (int d = 16; d > 0; d >>= 1)
        acc += __shfl_xor_sync(0xFFFFFFFFu, acc, d);
    if (lane == 0) g_s[v] = acc + style_b[i];

    if (blockIdx.x == 0) {
        for (int u = threadIdx.x; u < n_tail; u += 256)
            out_tail[u] = c_trg[u];
    }
}

// Fused wsq + demod + wm. Block = (b, o), thread = i.
__global__ __launch_bounds__(256)
void wmfused_kernel(const float* __restrict__ weight) {
    __shared__ float wsm[CIN * KS];    // 1280 floats, this o's weights [i][k]
    __shared__ float red[8];
    int bo = blockIdx.x;
    int b = bo >> 8;
    int o = bo & 255;
    int i = threadIdx.x;
    int lane = i & 31;
    int wrp = i >> 5;

    {
        const float4* src = (const float4*)(weight + (size_t)o * CIN * KS);
        float4* dst = (float4*)wsm;
        for (int u = threadIdx.x; u < (CIN * KS) / 4; u += 256)
            dst[u] = src[u];
    }
    __syncthreads();

    const float* wp = wsm + i * KS;    // stride 5: bank-conflict-free
    float w0 = wp[0], w1 = wp[1], w2 = wp[2], w3 = wp[3], w4 = wp[4];
    float s = g_s[b * CIN + i];
    float part = s * s * (w0 * w0 + w1 * w1 + w2 * w2 + w3 * w3 + w4 * w4);

#pragma unroll
    for (int d = 16; d > 0; d >>= 1)
        part += __shfl_xor_sync(0xFFFFFFFFu, part, d);
    if (lane == 0) red[wrp] = part;
    __syncthreads();
    float tot = red[lane & 7];
#pragma unroll
    for (int d = 4; d > 0; d >>= 1)
        tot += __shfl_xor_sync(0xFFFFFFFFu, tot, d);
    float demod = rsqrtf(tot + 1e-8f);

    float sd = s * demod;
    __half* dst = g_wm + ((size_t)b * KS * COUT + o) * CIN + i;
    dst[0 * (size_t)COUT * CIN] = __float2half_rn(w0 * sd);
    dst[1 * (size_t)COUT * CIN] = __float2half_rn(w1 * sd);
    dst[2 * (size_t)COUT * CIN] = __float2half_rn(w2 * sd);
    dst[3 * (size_t)COUT * CIN] = __float2half_rn(w3 * sd);
    dst[4 * (size_t)COUT * CIN] = __float2half_rn(w4 * sd);
}

// ---------------------------------------------------------------------------
__device__ __forceinline__ void mma16816(float* d, const unsigned* a,
                                         unsigned b0, unsigned b1) {
    asm volatile(
        "mma.sync.aligned.m16n8k16.row.col.f32.f16.f16.f32 "
        "{%0,%1,%2,%3}, {%4,%5,%6,%7}, {%8,%9}, {%0,%1,%2,%3};"
        : "+f"(d[0]), "+f"(d[1]), "+f"(d[2]), "+f"(d[3])
        : "r"(a[0]), "r"(a[1]), "r"(a[2]), "r"(a[3]), "r"(b0), "r"(b1));
}
__device__ __forceinline__ unsigned lds32(const __half* p) {
    return *(const unsigned*)p;
}
__device__ __forceinline__ uint32_t smem_u32(const void* p) {
    uint32_t a;
    asm("{ .reg .u64 t; cvta.to.shared.u64 t, %1; cvt.u32.u64 %0, t; }"
        : "=r"(a) : "l"(p));
    return a;
}
__device__ __forceinline__ void cp16(uint32_t dst, const void* src) {
    asm volatile("cp.async.cg.shared.global [%0], [%1], 16;"
                 :: "r"(dst), "l"(src));
}
#define CP_COMMIT() asm volatile("cp.async.commit_group;" ::: "memory")
#define CP_WAIT0()  asm volatile("cp.async.wait_group 0;" ::: "memory")

__device__ __forceinline__ float ldg_f32(const float* p) {
    float v;
    asm volatile("ld.global.nc.f32 %0, [%1];" : "=f"(v) : "l"(p));
    return v;
}

// ---------------------------------------------------------------------------
// Main conv: out[b,o,t] = leaky( sum_{i,k} Wm[b,o,i,k] * x_reflpad[b,i,t+k] )
// fp16 mma.sync, 256 threads = 64o x 256t, ICH=16, 2 CTAs/SM.
__global__ __launch_bounds__(NTH, 2)
void conv_kernel(const float* __restrict__ x, float* __restrict__ out) {
    extern __shared__ __align__(16) __half sm[];
    __half* xs = sm;                        // [2][XS_ST]
    __half* ws = sm + 2 * XS_ST;            // [2][WS_ST]
    const uint32_t ws_a = smem_u32(ws);

    const int b  = blockIdx.z;
    const int ob = blockIdx.y * OTI;
    const int tb = blockIdx.x * TTI;
    const int tid = threadIdx.x;
    const int wid = tid >> 5;
    const int lane = tid & 31;
    const int wo = wid & 1;           // o warp (2): 32 o each
    const int wt = wid >> 1;          // t warp (4): 64 t each
    const int lq = lane >> 2;
    const int lr = lane & 3;

    float acc[2][8][4];
#pragma unroll
    for (int mt = 0; mt < 2; ++mt)
#pragma unroll
        for (int nt = 0; nt < 8; ++nt)
#pragma unroll
            for (int e = 0; e < 4; ++e) acc[mt][nt][e] = 0.f;

    const float* xb = x + (size_t)b * CIN * TLEN;
    const __half* wmb = g_wm + (size_t)b * KS * COUT * CIN;

    float xr[17];

    // ---- prefetch Ws: 320 rows x 2 aligned 16B chunks = 640 cp16 ----
    auto prefetch_w = [&](int ic, int st) {
#pragma unroll
        for (int m = 0; m < 3; ++m) {
            int v = tid + NTH * m;
            if (v < 640) {
                int row = v >> 1;                    // k*OTI + o  (0..319)
                int c4  = v & 1;                     // 16B chunk within row
                int k = row >> 6;
                int o = row & 63;
                const __half* src =
                    wmb + ((size_t)(k * COUT + ob + o) * CIN + ic) + c4 * 8;
                uint32_t dst = ws_a + (uint32_t)(st * WS_ST + row * XR) * 2 + c4 * 16;
                cp16(dst, src);
            }
        }
        CP_COMMIT();
    };
    // ---- issue x LDGs for chunk into regs (latency hidden under MMAs) ----
    auto load_x = [&](int ic) {
#pragma unroll
        for (int j = 0; j < 17; ++j) {
            int u = tid + NTH * j;
            if (u < ICH * XT) {
                int i  = u / XT;
                int tl = u - i * XT;
                int t  = tb + tl - 2;
                t = (t < 0) ? -t : ((t >= TLEN) ? (2 * TLEN - 2 - t) : t);
                xr[j] = ldg_f32(xb + (size_t)(ic + i) * TLEN + t);
            }
        }
    };
    // ---- convert + store x regs into stage st ----
    auto store_x = [&](int st) {
#pragma unroll
        for (int j = 0; j < 17; ++j) {
            int u = tid + NTH * j;
            if (u < ICH * XT) {
                int i  = u / XT;
                int tl = u - i * XT;
                xs[st * XS_ST + tl * XR + i] = __float2half_rn(xr[j]);
            }
        }
    };

    // ---- prologue: fill stage 0 ----
    prefetch_w(0, 0);
    load_x(0);
    store_x(0);
    CP_WAIT0();
    __syncthreads();

    for (int c = 0; c < NCH; ++c) {
        const int st = c & 1;
        const int nst = st ^ 1;
        if (c + 1 < NCH) {
            prefetch_w((c + 1) * ICH, nst);
            load_x((c + 1) * ICH);
        }

        // ---- MMA over stage st (single k16 per chunk) ----
        const __half* wsp = ws + st * WS_ST;
        const __half* xsp = xs + st * XS_ST;

#pragma unroll
        for (int tap = 0; tap < KS; ++tap) {
            unsigned ah[2][4];
#pragma unroll
            for (int mt = 0; mt < 2; ++mt) {
                int row = tap * OTI + wo * 32 + mt * 16 + lq;
                int col = lr * 2;
                const __half* ph = wsp + row * XR + col;
                ah[mt][0] = lds32(ph);
                ah[mt][1] = lds32(ph + 8 * XR);
                ah[mt][2] = lds32(ph + 8);
                ah[mt][3] = lds32(ph + 8 * XR + 8);
            }
#pragma unroll
            for (int nt = 0; nt < 8; ++nt) {
                int trow = wt * 64 + nt * 8 + lq + tap;
                int col  = lr * 2;
                const __half* ph = xsp + trow * XR + col;
                unsigned bh0 = lds32(ph), bh1 = lds32(ph + 8);
#pragma unroll
                for (int mt = 0; mt < 2; ++mt)
                    mma16816(acc[mt][nt], ah[mt], bh0, bh1);
            }
        }

        if (c + 1 < NCH) {
            store_x(nst);
            CP_WAIT0();
        }
        __syncthreads();
    }

    // ---- epilogue: leaky relu + store ----
#pragma unroll
    for (int mt = 0; mt < 2; ++mt) {
#pragma unroll
        for (int nt = 0; nt < 8; ++nt) {
            int o0 = ob + wo * 32 + mt * 16 + lq;
            int t0 = tb + wt * 64 + nt * 8 + lr * 2;
            float z0 = acc[mt][nt][0], z1 = acc[mt][nt][1];
            float z2 = acc[mt][nt][2], z3 = acc[mt][nt][3];
            z0 = (z0 > 0.f) ? z0 : 0.2f * z0;
            z1 = (z1 > 0.f) ? z1 : 0.2f * z1;
            z2 = (z2 > 0.f) ? z2 : 0.2f * z2;
            z3 = (z3 > 0.f) ? z3 : 0.2f * z3;
            float* p0 = out + ((size_t)b * COUT + o0) * TLEN + t0;
            *(float2*)p0 = make_float2(z0, z1);
            *(float2*)(p0 + 8 * TLEN) = make_float2(z2, z3);
        }
    }
}

// ---------------------------------------------------------------------------
extern "C" void kernel_launch(void* const* d_in, const int* in_sizes, int n_in,
                              void* d_out, int out_size) {
    const float* x       = (const float*)d_in[0];   // [16,256,8192]
    const float* c_trg   = (const float*)d_in[1];   // [16,128]
    const float* style_w = (const float*)d_in[2];   // [256,128]
    const float* style_b = (const float*)d_in[3];   // [256]
    const float* weight  = (const float*)d_in[4];   // [1,256,256,5]
    float* out = (float*)d_out;

    size_t conv_elems = (size_t)NB * COUT * TLEN;   // 33,554,432
    int n_tail = ((size_t)out_size > conv_elems)
               ? (int)((size_t)out_size - conv_elems) : 0;

    style_kernel<<<(NB * CIN) / 8, 256>>>(c_trg, style_w, style_b,
                                          out + conv_elems, n_tail);
    wmfused_kernel<<<NB * COUT, 256>>>(weight);

    static bool attr_done = false;
    if (!attr_done) {
        cudaFuncSetAttribute(conv_kernel,
                             cudaFuncAttributeMaxDynamicSharedMemorySize,
                             SMEM_BYTES);
        attr_done = true;
    }
    dim3 grid(TLEN / TTI, COUT / OTI, NB);        // (32, 4, 16)
    conv_kernel<<<grid, NTH, SMEM_BYTES>>>(x, out);
}

// round 17
// speedup vs baseline: 2.0992x; 2.0992x over previous
#include <cuda_runtime.h>
#include <cuda_fp16.h>
#include <cstdint>

#define NB   16
#define CIN  256
#define COUT 256
#define KS   5
#define SPK  128
#define TLEN 8192

#define OTI  128     // o tile per block (4 o-warps)
#define TTI  256     // t tile per block (4 t-warps)
#define ICH  32      // i chunk
#define XR   40      // padded row pitch (80B; 20-word stride -> LDSM conflict-free)
#define XT   260     // xs rows (t range: tile + 4 pad)
#define NCH  8       // CIN / ICH
#define NTH  512

#define XS_ST (XT * XR)              // 10400 elems per stage
#define WS_ST (KS * OTI * XR)        // 25600 elems per stage
#define SMEM_BYTES ((2 * XS_ST + 2 * WS_ST) * 2)   // 144000

// scratch (no cudaMalloc allowed)
__device__ float g_s[NB * CIN];
__device__ __half g_wm[(size_t)NB * KS * COUT * CIN];        // [b][k][o][i]

// ---------------------------------------------------------------------------
// style GEMV, one warp per (b, i); block 0 copies the c_trg passthrough tail.
__global__ __launch_bounds__(256)
void style_kernel(const float* __restrict__ c_trg,
                  const float* __restrict__ style_w,
                  const float* __restrict__ style_b,
                  float* __restrict__ out_tail, int n_tail) {
    int v = blockIdx.x * 8 + (threadIdx.x >> 5);   // warp index: b*CIN + i
    int lane = threadIdx.x & 31;
    int b = v >> 8;
    int i = v & 255;
    const float* c = c_trg + b * SPK;
    const float* w = style_w + i * SPK;
    float acc = 0.f;
#pragma unroll
    for (int j = 0; j < 4; ++j) {
        int idx = lane + j * 32;
        acc += c[idx] * w[idx];
    }
#pragma unroll
    for (int d = 16; d > 0; d >>= 1)
        acc += __shfl_xor_sync(0xFFFFFFFFu, acc, d);
    if (lane == 0) g_s[v] = acc + style_b[i];

    if (blockIdx.x == 0) {
        for (int u = threadIdx.x; u < n_tail; u += 256)
            out_tail[u] = c_trg[u];
    }
}

// Fused wsq + demod + wm. Block = (b, o), thread = i.
__global__ __launch_bounds__(256)
void wmfused_kernel(const float* __restrict__ weight) {
    __shared__ float wsm[CIN * KS];    // 1280 floats, this o's weights [i][k]
    __shared__ float red[8];
    int bo = blockIdx.x;
    int b = bo >> 8;
    int o = bo & 255;
    int i = threadIdx.x;
    int lane = i & 31;
    int wrp = i >> 5;

    {
        const float4* src = (const float4*)(weight + (size_t)o * CIN * KS);
        float4* dst = (float4*)wsm;
        for (int u = threadIdx.x; u < (CIN * KS) / 4; u += 256)
            dst[u] = src[u];
    }
    __syncthreads();

    const float* wp = wsm + i * KS;    // stride 5: bank-conflict-free
    float w0 = wp[0], w1 = wp[1], w2 = wp[2], w3 = wp[3], w4 = wp[4];
    float s = g_s[b * CIN + i];
    float part = s * s * (w0 * w0 + w1 * w1 + w2 * w2 + w3 * w3 + w4 * w4);

#pragma unroll
    for (int d = 16; d > 0; d >>= 1)
        part += __shfl_xor_sync(0xFFFFFFFFu, part, d);
    if (lane == 0) red[wrp] = part;
    __syncthreads();
    float tot = red[lane & 7];
#pragma unroll
    for (int d = 4; d > 0; d >>= 1)
        tot += __shfl_xor_sync(0xFFFFFFFFu, tot, d);
    float demod = rsqrtf(tot + 1e-8f);

    float sd = s * demod;
    __half* dst = g_wm + ((size_t)b * KS * COUT + o) * CIN + i;
    dst[0 * (size_t)COUT * CIN] = __float2half_rn(w0 * sd);
    dst[1 * (size_t)COUT * CIN] = __float2half_rn(w1 * sd);
    dst[2 * (size_t)COUT * CIN] = __float2half_rn(w2 * sd);
    dst[3 * (size_t)COUT * CIN] = __float2half_rn(w3 * sd);
    dst[4 * (size_t)COUT * CIN] = __float2half_rn(w4 * sd);
}

// ---------------------------------------------------------------------------
__device__ __forceinline__ void mma16816(float* d, const unsigned* a,
                                         unsigned b0, unsigned b1) {
    asm volatile(
        "mma.sync.aligned.m16n8k16.row.col.f32.f16.f16.f32 "
        "{%0,%1,%2,%3}, {%4,%5,%6,%7}, {%8,%9}, {%0,%1,%2,%3};"
        : "+f"(d[0]), "+f"(d[1]), "+f"(d[2]), "+f"(d[3])
        : "r"(a[0]), "r"(a[1]), "r"(a[2]), "r"(a[3]), "r"(b0), "r"(b1));
}
__device__ __forceinline__ void ldsm_x4(unsigned& r0, unsigned& r1,
                                        unsigned& r2, unsigned& r3,
                                        uint32_t addr) {
    asm volatile("ldmatrix.sync.aligned.m8n8.x4.shared.b16 {%0,%1,%2,%3}, [%4];"
                 : "=r"(r0), "=r"(r1), "=r"(r2), "=r"(r3) : "r"(addr));
}
__device__ __forceinline__ uint32_t smem_u32(const void* p) {
    uint32_t a;
    asm("{ .reg .u64 t; cvta.to.shared.u64 t, %1; cvt.u32.u64 %0, t; }"
        : "=r"(a) : "l"(p));
    return a;
}
__device__ __forceinline__ void cp16(uint32_t dst, const void* src) {
    asm volatile("cp.async.cg.shared.global [%0], [%1], 16;"
                 :: "r"(dst), "l"(src));
}
#define CP_COMMIT() asm volatile("cp.async.commit_group;" ::: "memory")
#define CP_WAIT0()  asm volatile("cp.async.wait_group 0;" ::: "memory")

__device__ __forceinline__ float ldg_f32(const float* p) {
    float v;
    asm volatile("ld.global.nc.f32 %0, [%1];" : "=f"(v) : "l"(p));
    return v;
}

// ---------------------------------------------------------------------------
// Main conv: out[b,o,t] = leaky( sum_{i,k} Wm[b,o,i,k] * x_reflpad[b,i,t+k] )
// fp16 mma.sync + ldmatrix fragments, 512 threads = 128o x 256t, dbl-buffered.
__global__ __launch_bounds__(NTH, 1)
void conv_kernel(const float* __restrict__ x, float* __restrict__ out) {
    extern __shared__ __align__(16) __half sm[];
    __half* xs = sm;                        // [2][XS_ST]
    __half* ws = sm + 2 * XS_ST;            // [2][WS_ST]
    const uint32_t xs_a = smem_u32(xs);
    const uint32_t ws_a = smem_u32(ws);

    const int b  = blockIdx.z;
    const int ob = blockIdx.y * OTI;
    const int tb = blockIdx.x * TTI;
    const int tid = threadIdx.x;
    const int lane = tid & 31;
    const int wid = tid >> 5;
    const int wo = wid & 3;           // o warp (4): 32 o each
    const int wt = wid >> 2;          // t warp (4): 64 t each
    const int lq = lane >> 2;
    const int lr = lane & 3;

    // per-lane ldmatrix row/col constants
    // A (.x4 = 16x16): tiles = {rows0-7,k0},{rows8-15,k0},{rows0-7,k8},{rows8-15,k8}
    const int arow = wo * 32 + ((lane >> 3) & 1) * 8 + (lane & 7);
    const int acol = (lane >> 4) * 8;
    // B (.x4 = 2 nt x 16k): tiles = {nt0,k0},{nt0,k8},{nt1,k0},{nt1,k8}
    const int brow = wt * 64 + (lane >> 4) * 8 + (lane & 7);
    const int bcol = ((lane >> 3) & 1) * 8;

    float acc[2][8][4];
#pragma unroll
    for (int mt = 0; mt < 2; ++mt)
#pragma unroll
        for (int nt = 0; nt < 8; ++nt)
#pragma unroll
            for (int e = 0; e < 4; ++e) acc[mt][nt][e] = 0.f;

    const float* xb = x + (size_t)b * CIN * TLEN;
    const __half* wmb = g_wm + (size_t)b * KS * COUT * CIN;

    float xr[17];

    // ---- prefetch Ws: 640 rows x 4 aligned 16B chunks = 2560 cp16 ----
    auto prefetch_w = [&](int ic, int st) {
#pragma unroll
        for (int m = 0; m < 5; ++m) {
            int v = tid + NTH * m;                  // < 2560
            int row = v >> 2;                        // k*OTI + o  (0..639)
            int c4  = v & 3;
            int k = row >> 7;
            int o = row & 127;
            const __half* src =
                wmb + ((size_t)(k * COUT + ob + o) * CIN + ic) + c4 * 8;
            uint32_t dst = ws_a + (uint32_t)(st * WS_ST + row * XR) * 2 + c4 * 16;
            cp16(dst, src);
        }
        CP_COMMIT();
    };
    auto load_x = [&](int ic) {
#pragma unroll
        for (int j = 0; j < 17; ++j) {
            int u = tid + NTH * j;
            if (u < ICH * XT) {
                int i  = u / XT;
                int tl = u - i * XT;
                int t  = tb + tl - 2;
                t = (t < 0) ? -t : ((t >= TLEN) ? (2 * TLEN - 2 - t) : t);
                xr[j] = ldg_f32(xb + (size_t)(ic + i) * TLEN + t);
            }
        }
    };
    auto store_x = [&](int st) {
#pragma unroll
        for (int j = 0; j < 17; ++j) {
            int u = tid + NTH * j;
            if (u < ICH * XT) {
                int i  = u / XT;
                int tl = u - i * XT;
                xs[st * XS_ST + tl * XR + i] = __float2half_rn(xr[j]);
            }
        }
    };

    // ---- prologue: fill stage 0 ----
    prefetch_w(0, 0);
    load_x(0);
    store_x(0);
    CP_WAIT0();
    __syncthreads();

    for (int c = 0; c < NCH; ++c) {
        const int st = c & 1;
        const int nst = st ^ 1;
        if (c + 1 < NCH) {
            prefetch_w((c + 1) * ICH, nst);
            load_x((c + 1) * ICH);
        }

        // ---- MMA over stage st ----
        const uint32_t wsa_st = ws_a + (uint32_t)(st * WS_ST) * 2;
        const uint32_t xsa_st = xs_a + (uint32_t)(st * XS_ST) * 2;

        for (int tap = 0; tap < KS; ++tap) {
#pragma unroll
            for (int k16 = 0; k16 < ICH; k16 += 16) {
                unsigned ah[2][4];
#pragma unroll
                for (int mt = 0; mt < 2; ++mt) {
                    uint32_t aaddr = wsa_st +
                        (uint32_t)((tap * OTI + mt * 16 + arow) * XR + k16 + acol) * 2;
                    ldsm_x4(ah[mt][0], ah[mt][1], ah[mt][2], ah[mt][3], aaddr);
                }
#pragma unroll
                for (int p = 0; p < 4; ++p) {
                    unsigned b0, b1, b2, b3;
                    uint32_t baddr = xsa_st +
                        (uint32_t)((p * 16 + brow + tap) * XR + k16 + bcol) * 2;
                    ldsm_x4(b0, b1, b2, b3, baddr);
#pragma unroll
                    for (int mt = 0; mt < 2; ++mt) {
                        mma16816(acc[mt][2 * p + 0], ah[mt], b0, b1);
                        mma16816(acc[mt][2 * p + 1], ah[mt], b2, b3);
                    }
                }
            }
        }

        if (c + 1 < NCH) {
            store_x(nst);
            CP_WAIT0();
        }
        __syncthreads();
    }

    // ---- epilogue: leaky relu + store ----
#pragma unroll
    for (int mt = 0; mt < 2; ++mt) {
#pragma unroll
        for (int nt = 0; nt < 8; ++nt) {
            int o0 = ob + wo * 32 + mt * 16 + lq;
            int t0 = tb + wt * 64 + nt * 8 + lr * 2;
            float z0 = acc[mt][nt][0], z1 = acc[mt][nt][1];
            float z2 = acc[mt][nt][2], z3 = acc[mt][nt][3];
            z0 = (z0 > 0.f) ? z0 : 0.2f * z0;
            z1 = (z1 > 0.f) ? z1 : 0.2f * z1;
            z2 = (z2 > 0.f) ? z2 : 0.2f * z2;
            z3 = (z3 > 0.f) ? z3 : 0.2f * z3;
            float* p0 = out + ((size_t)b * COUT + o0) * TLEN + t0;
            *(float2*)p0 = make_float2(z0, z1);
            *(float2*)(p0 + 8 * TLEN) = make_float2(z2, z3);
        }
    }
}

// ---------------------------------------------------------------------------
extern "C" void kernel_launch(void* const* d_in, const int* in_sizes, int n_in,
                              void* d_out, int out_size) {
    const float* x       = (const float*)d_in[0];   // [16,256,8192]
    const float* c_trg   = (const float*)d_in[1];   // [16,128]
    const float* style_w = (const float*)d_in[2];   // [256,128]
    const float* style_b = (const float*)d_in[3];   // [256]
    const float* weight  = (const float*)d_in[4];   // [1,256,256,5]
    float* out = (float*)d_out;

    size_t conv_elems = (size_t)NB * COUT * TLEN;   // 33,554,432
    int n_tail = ((size_t)out_size > conv_elems)
               ? (int)((size_t)out_size - conv_elems) : 0;

    style_kernel<<<(NB * CIN) / 8, 256>>>(c_trg, style_w, style_b,
                                          out + conv_elems, n_tail);
    wmfused_kernel<<<NB * COUT, 256>>>(weight);

    static bool attr_done = false;
    if (!attr_done) {
        cudaFuncSetAttribute(conv_kernel,
                             cudaFuncAttributeMaxDynamicSharedMemorySize,
                             SMEM_BYTES);
        attr_done = true;
    }
    dim3 grid(TLEN / TTI, COUT / OTI, NB);        // (32, 2, 16)
    conv_kernel<<<grid, NTH, SMEM_BYTES>>>(x, out);
}